// round 8
// baseline (speedup 1.0000x reference)
#include <cuda_runtime.h>
#include <cstdint>
#include <math.h>

#define B_DIM  16384
#define ZD     128
#define HD     512
#define TSTEPS 32

// ---------------- device global scratch ----------------
__device__ __align__(16) float    g_W1c[HD * HD];               // W1[128:640,:] tf32 (ctxproj)
__device__ __align__(16) float    g_ctxr[(size_t)B_DIM * HD];   // ctx tf32 (ctxproj)
__device__ __align__(16) uint32_t g_ctxpb[(size_t)B_DIM * 256]; // ctxproj, packed bf16x2 pairs
__device__ __align__(16) uint32_t g_Wsl[32 * 2048];             // 32 weight slices, bf16x2 [16q][128n]
__device__ double g_sum;

// ---------------- helpers ----------------
__device__ __forceinline__ float rna(float x) {
    float r; asm("cvt.rna.tf32.f32 %0, %1;" : "=f"(r) : "f"(x)); return r;
}
__device__ __forceinline__ uint32_t packbf(float lo, float hi) {
    uint32_t r; asm("cvt.rn.bf16x2.f32 %0, %1, %2;" : "=r"(r) : "f"(hi), "f"(lo)); return r;
}
__device__ __forceinline__ float bflo(uint32_t u) { return __uint_as_float(u << 16); }
__device__ __forceinline__ float bfhi(uint32_t u) { return __uint_as_float(u & 0xFFFF0000u); }
__device__ __forceinline__ uint32_t sptr(const void* p) {
    return (uint32_t)__cvta_generic_to_shared(p);
}
__device__ __forceinline__ void cp16(uint32_t d, const void* s) {
    asm volatile("cp.async.cg.shared.global [%0], [%1], 16;" :: "r"(d), "l"(s));
}
#define CP_COMMIT() asm volatile("cp.async.commit_group;" ::: "memory")

#define MMA_TF32(acc, af, bf) \
    asm volatile("mma.sync.aligned.m16n8k8.row.col.f32.tf32.tf32.f32 " \
        "{%0,%1,%2,%3}, {%4,%5,%6,%7}, {%8,%9}, {%0,%1,%2,%3};" \
        : "+f"((acc)[0]), "+f"((acc)[1]), "+f"((acc)[2]), "+f"((acc)[3]) \
        : "r"((af)[0]), "r"((af)[1]), "r"((af)[2]), "r"((af)[3]), \
          "r"((bf)[0]), "r"((bf)[1]))

#define MMA_BF16(acc, af, b0, b1) \
    asm volatile("mma.sync.aligned.m16n8k16.row.col.f32.bf16.bf16.f32 " \
        "{%0,%1,%2,%3}, {%4,%5,%6,%7}, {%8,%9}, {%0,%1,%2,%3};" \
        : "+f"((acc)[0]), "+f"((acc)[1]), "+f"((acc)[2]), "+f"((acc)[3]) \
        : "r"((af)[0]), "r"((af)[1]), "r"((af)[2]), "r"((af)[3]), \
          "r"(b0), "r"(b1))

// ================= ctxproj tf32 GEMM (proven core, unchanged) =================
#define ASTR 20
#define BSTR 136

struct SmemT {
    float As[2][128][ASTR];
    float Bs[2][16][BSTR];
};

__device__ __forceinline__ void gemm_core(
    SmemT* s, const float* __restrict__ A, int lda,
    const float* __restrict__ Bm, int ldb, int K, float acc[2][8][4])
{
    const int tid = threadIdx.x;
    const int lane = tid & 31;
    const int w = tid >> 5, wm = w >> 1, wn = w & 1;
    const int nch = K / 16;

    #pragma unroll
    for (int i = 0; i < 2; i++) {
        int lin = tid + i * 256;
        int r = lin >> 2, kq = (lin & 3) * 4;
        cp16(sptr(&s->As[0][r][kq]), A + (size_t)r * lda + kq);
    }
    #pragma unroll
    for (int i = 0; i < 2; i++) {
        int lin = tid + i * 256;
        int kr = lin >> 5, nq = (lin & 31) * 4;
        cp16(sptr(&s->Bs[0][kr][nq]), Bm + (size_t)kr * ldb + nq);
    }
    CP_COMMIT();

    for (int c = 0; c < nch; c++) {
        const int buf = c & 1;
        if (c + 1 < nch) {
            const int k0 = (c + 1) * 16;
            #pragma unroll
            for (int i = 0; i < 2; i++) {
                int lin = tid + i * 256;
                int r = lin >> 2, kq = (lin & 3) * 4;
                cp16(sptr(&s->As[buf ^ 1][r][kq]), A + (size_t)r * lda + k0 + kq);
            }
            #pragma unroll
            for (int i = 0; i < 2; i++) {
                int lin = tid + i * 256;
                int kr = lin >> 5, nq = (lin & 31) * 4;
                cp16(sptr(&s->Bs[buf ^ 1][kr][nq]), Bm + (size_t)(k0 + kr) * ldb + nq);
            }
            CP_COMMIT();
            asm volatile("cp.async.wait_group 1;" ::: "memory");
        } else {
            asm volatile("cp.async.wait_group 0;" ::: "memory");
        }
        __syncthreads();

        #pragma unroll
        for (int kk = 0; kk < 16; kk += 8) {
            uint32_t af[2][4], bf[8][2];
            const int kb = kk + (lane & 3);
            #pragma unroll
            for (int mt = 0; mt < 2; mt++) {
                int r = wm * 32 + mt * 16 + (lane >> 2);
                af[mt][0] = __float_as_uint(s->As[buf][r][kb]);
                af[mt][1] = __float_as_uint(s->As[buf][r + 8][kb]);
                af[mt][2] = __float_as_uint(s->As[buf][r][kb + 4]);
                af[mt][3] = __float_as_uint(s->As[buf][r + 8][kb + 4]);
            }
            #pragma unroll
            for (int nt = 0; nt < 8; nt++) {
                int nn = wn * 64 + nt * 8 + (lane >> 2);
                bf[nt][0] = __float_as_uint(s->Bs[buf][kb][nn]);
                bf[nt][1] = __float_as_uint(s->Bs[buf][kb + 4][nn]);
            }
            #pragma unroll
            for (int mt = 0; mt < 2; mt++)
                #pragma unroll
                for (int nt = 0; nt < 8; nt++)
                    MMA_TF32(acc[mt][nt], af[mt], bf[nt]);
        }
        __syncthreads();
    }
}

__global__ void __launch_bounds__(256, 2) ctxproj_kernel(const float* __restrict__ b1)
{
    __shared__ SmemT s;
    float acc[2][8][4] = {};
    const int brow = blockIdx.y, bcol = blockIdx.x;
    gemm_core(&s, g_ctxr + (size_t)brow * 128 * HD, HD, g_W1c + bcol * 128, HD, HD, acc);

    const int lane = threadIdx.x & 31;
    const int w = threadIdx.x >> 5, wm = w >> 1, wn = w & 1;
    #pragma unroll
    for (int mt = 0; mt < 2; mt++) {
        #pragma unroll
        for (int nt = 0; nt < 8; nt++) {
            int r = brow * 128 + wm * 32 + mt * 16 + (lane >> 2);
            int c = bcol * 128 + wn * 64 + nt * 8 + 2 * (lane & 3);
            float2 bv = *reinterpret_cast<const float2*>(&b1[c]);
            g_ctxpb[(size_t)r * 256 + (c >> 1)] =
                packbf(acc[mt][nt][0] + bv.x, acc[mt][nt][1] + bv.y);
            g_ctxpb[(size_t)(r + 8) * 256 + (c >> 1)] =
                packbf(acc[mt][nt][2] + bv.x, acc[mt][nt][3] + bv.y);
        }
    }
}

// ================= persistent bf16 step kernel =================
// 16 warps (4m x 4n), warp tile 32x32, CTA tile 128 rows.
struct PS {
    float    zf[128][130];    // fp32 z state           66560 B
    uint32_t zb[128][68];     // bf16x2 z pairs         34816 B
    uint32_t hb[128][68];     // bf16x2 h chunk pairs   34816 B
    uint32_t wb[5][16][136];  // weight slice ring      43520 B
};
#define PS_SZ ((int)sizeof(PS))

extern __shared__ char dynsm[];

__device__ __forceinline__ void mma_slice(
    float acc[2][4][4], const uint32_t (&A)[128][68], int qb,
    const uint32_t (&Bm)[16][136], int lane, int wm, int wn)
{
    #pragma unroll
    for (int kt = 0; kt < 2; kt++) {
        const int qa = qb + kt * 8 + (lane & 3);
        uint32_t af[2][4];
        #pragma unroll
        for (int mt = 0; mt < 2; mt++) {
            int r = wm * 32 + mt * 16 + (lane >> 2);
            af[mt][0] = A[r][qa];
            af[mt][1] = A[r + 8][qa];
            af[mt][2] = A[r][qa + 4];
            af[mt][3] = A[r + 8][qa + 4];
        }
        const int kq = kt * 8 + (lane & 3);
        #pragma unroll
        for (int nt = 0; nt < 4; nt++) {
            int nn = wn * 32 + nt * 8 + (lane >> 2);
            uint32_t b0 = Bm[kq][nn];
            uint32_t b1 = Bm[kq + 4][nn];
            #pragma unroll
            for (int mt = 0; mt < 2; mt++)
                MMA_BF16(acc[mt][nt], af[mt], b0, b1);
        }
    }
}

__global__ void __launch_bounds__(512, 1) step_kernel(
    const float* __restrict__ eps0, const float* __restrict__ eps,
    const float* __restrict__ beta, const float* __restrict__ sigma0,
    const float* __restrict__ b2,   const float* __restrict__ temb,
    const float* __restrict__ tmu)
{
    PS* s = (PS*)dynsm;
    const int tid = threadIdx.x, lane = tid & 31, w = tid >> 5;
    const int wm = w >> 2, wn = w & 3;
    const int grow0 = blockIdx.x * 128;

    const float s0 = sigma0[0];
    const float lg = logf(s0);
    const float dt = 1.0f / TSTEPS;
    double ssum = 0.0;

    // ---- init z (fp32 + bf16 copy) + prior-correction term ----
    {
        float local = 0.f;
        #pragma unroll
        for (int i = 0; i < 8; i++) {
            int lin = (tid + i * 512) * 4;
            int row = lin >> 7, col = lin & 127;
            float4 e = *reinterpret_cast<const float4*>(&eps0[(size_t)(grow0 + row) * ZD + col]);
            float z0 = s0 * e.x, z1 = s0 * e.y, z2 = s0 * e.z, z3 = s0 * e.w;
            s->zf[row][col + 0] = z0; s->zf[row][col + 1] = z1;
            s->zf[row][col + 2] = z2; s->zf[row][col + 3] = z3;
            s->zb[row][(col >> 1) + 0] = packbf(z0, z1);
            s->zb[row][(col >> 1) + 1] = packbf(z2, z3);
            local += 0.5f * (e.x * e.x + e.y * e.y + e.z * e.z + e.w * e.w) + 4.f * lg;
        }
        ssum += (double)local;
    }

    // ---- prologue: prefetch slices 0..3 into ring slots 0..3 ----
    #pragma unroll
    for (int g = 0; g < 4; g++) {
        const uint32_t* src = g_Wsl + (g & 31) * 2048;
        uint32_t dstb = sptr(&s->wb[g % 5][0][0]);
        int l4 = tid * 4;
        cp16(dstb + (uint32_t)(((l4 >> 7) * 136 + (l4 & 127)) * 4), src + l4);
        CP_COMMIT();
    }

#define SLICE_PRE(gv) do { \
    asm volatile("cp.async.wait_group 3;" ::: "memory"); \
    __syncthreads(); \
    const uint32_t* _src = g_Wsl + (((gv) + 4) & 31) * 2048; \
    uint32_t _dst = sptr(&s->wb[((gv) + 4) % 5][0][0]); \
    int _l4 = tid * 4; \
    cp16(_dst + (uint32_t)(((_l4 >> 7) * 136 + (_l4 & 127)) * 4), _src + _l4); \
    CP_COMMIT(); \
} while (0)

    int g = 0;
    for (int t = 0; t < TSTEPS; t++) {
        const float beta_f = __ldg(&beta[t]);
        const float beta_b = __ldg(&beta[(t + TSTEPS - 1) % TSTEPS]);
        const float sig_f = sqrtf(2.0f * beta_f * dt) * s0;
        const float sig_b = sqrtf(2.0f * beta_b * dt) * s0;
        const float inv_sb = 1.0f / sig_b;
        const float logdiff = logf(sig_f) - logf(sig_b);

        float accu[2][4][4] = {};

        for (int c = 0; c < 4; c++) {
            // prefetch ctxpb for this chunk into registers (consumed in epilogue1)
            uint32_t cpr[4][2][2];
            #pragma unroll
            for (int nt = 0; nt < 4; nt++) {
                int lq = wn * 16 + nt * 4 + (lane & 3);
                #pragma unroll
                for (int mt = 0; mt < 2; mt++) {
                    int r = wm * 32 + mt * 16 + (lane >> 2);
                    #pragma unroll
                    for (int hf = 0; hf < 2; hf++) {
                        int rr = r + 8 * hf;
                        cpr[nt][mt][hf] =
                            __ldg(&g_ctxpb[(size_t)(grow0 + rr) * 256 + c * 64 + lq]);
                    }
                }
            }

            float acch[2][4][4] = {};
            #pragma unroll
            for (int kc = 0; kc < 4; kc++) {
                SLICE_PRE(g);
                mma_slice(acch, s->zb, kc * 16, s->wb[g % 5], lane, wm, wn);
                g++;
            }
            // ---- epilogue1: h = bf16(relu(acch + ctxp + te)) -> hb ----
            #pragma unroll
            for (int nt = 0; nt < 4; nt++) {
                int gc = c * 128 + wn * 32 + nt * 8 + 2 * (lane & 3);
                float2 te = *reinterpret_cast<const float2*>(&temb[(size_t)t * HD + gc]);
                int lq = wn * 16 + nt * 4 + (lane & 3);
                #pragma unroll
                for (int mt = 0; mt < 2; mt++) {
                    int r = wm * 32 + mt * 16 + (lane >> 2);
                    #pragma unroll
                    for (int hf = 0; hf < 2; hf++) {
                        int rr = r + 8 * hf;
                        uint32_t cpv = cpr[nt][mt][hf];
                        float v0 = acch[mt][nt][hf * 2 + 0] + bflo(cpv) + te.x;
                        float v1 = acch[mt][nt][hf * 2 + 1] + bfhi(cpv) + te.y;
                        s->hb[rr][lq] = packbf(fmaxf(v0, 0.f), fmaxf(v1, 0.f));
                    }
                }
            }
            #pragma unroll
            for (int kc = 0; kc < 4; kc++) {
                SLICE_PRE(g);
                mma_slice(accu, s->hb, kc * 16, s->wb[g % 5], lane, wm, wn);
                g++;
            }
        }

        // ---- update epilogue ----
        const float* eps_t = eps + ((size_t)t * B_DIM + grow0) * ZD;
        float local = 0.f;
        #pragma unroll
        for (int nt = 0; nt < 4; nt++) {
            int cc = wn * 32 + nt * 8 + 2 * (lane & 3);
            float2 bv = *reinterpret_cast<const float2*>(&b2[cc]);
            #pragma unroll
            for (int mt = 0; mt < 2; mt++) {
                int r = wm * 32 + mt * 16 + (lane >> 2);
                #pragma unroll
                for (int hf = 0; hf < 2; hf++) {
                    int rr = r + 8 * hf;
                    float2 zp = *reinterpret_cast<const float2*>(&s->zf[rr][cc]);
                    float2 ev = *reinterpret_cast<const float2*>(&eps_t[(size_t)rr * ZD + cc]);
                    float u0 = accu[mt][nt][hf * 2 + 0] + bv.x;
                    float u1 = accu[mt][nt][hf * 2 + 1] + bv.y;
                    float mu0 = zp.x + (beta_f * zp.x + u0) * dt;
                    float mu1 = zp.y + (beta_f * zp.y + u1) * dt;
                    float zn0 = fmaf(sig_f, ev.x, mu0);
                    float zn1 = fmaf(sig_f, ev.y, mu1);
                    float mb0 = zn0 - beta_b * zn0 * dt;
                    float mb1 = zn1 - beta_b * zn1 * dt;
                    float a10 = (zp.x - mb0) * inv_sb;
                    float a11 = (zp.y - mb1) * inv_sb;
                    local += 0.5f * (ev.x * ev.x - a10 * a10) + logdiff;
                    local += 0.5f * (ev.y * ev.y - a11 * a11) + logdiff;
                    if (t == TSTEPS - 1) {
                        float2 tm = *reinterpret_cast<const float2*>(
                            &tmu[(size_t)(grow0 + rr) * ZD + cc]);
                        float d0 = zn0 - tm.x, d1 = zn1 - tm.y;
                        local -= 0.5f * (d0 * d0 + d1 * d1);
                    }
                    float2 zo = { zn0, zn1 };
                    *reinterpret_cast<float2*>(&s->zf[rr][cc]) = zo;
                    s->zb[rr][cc >> 1] = packbf(zn0, zn1);
                }
            }
        }
        ssum += (double)local;
    }

    // ---- reduce ----
    asm volatile("cp.async.wait_group 0;" ::: "memory");
    __syncthreads();
    double* red = reinterpret_cast<double*>(&s->wb[0][0][0]);
    red[tid] = ssum;
    __syncthreads();
    for (int st = 256; st > 0; st >>= 1) {
        if (tid < st) red[tid] += red[tid + st];
        __syncthreads();
    }
    if (tid == 0) atomicAdd(&g_sum, red[0]);
}

// ---------------- prep / finalize ----------------
__global__ void prep_w1c(const float* __restrict__ W1)
{
    const int N = HD * HD;
    for (int i = blockIdx.x * blockDim.x + threadIdx.x; i < N; i += gridDim.x * blockDim.x)
        g_W1c[i] = rna(W1[ZD * HD + i]);
}
__global__ void prep_ctx(const float* __restrict__ ctx)
{
    const size_t N = (size_t)B_DIM * HD;
    size_t i0 = (size_t)blockIdx.x * blockDim.x + threadIdx.x;
    if (i0 == 0) g_sum = 0.0;
    for (size_t i = i0; i < N; i += (size_t)gridDim.x * blockDim.x)
        g_ctxr[i] = rna(ctx[i]);
}
// build packed bf16 weight slices: slice si: c=si>>3, ph=(si>>2)&1, kc=si&3
__global__ void prep_slices(const float* __restrict__ W1, const float* __restrict__ W2)
{
    int idx = blockIdx.x * blockDim.x + threadIdx.x;
    if (idx >= 32 * 2048) return;
    int si = idx >> 11, rem = idx & 2047;
    int q = rem >> 7, n = rem & 127;
    int c = si >> 3, ph = (si >> 2) & 1, kc = si & 3;
    float v0, v1;
    if (!ph) {
        int k0 = kc * 32 + 2 * q;
        v0 = W1[(size_t)k0 * HD + c * 128 + n];
        v1 = W1[(size_t)(k0 + 1) * HD + c * 128 + n];
    } else {
        int k0 = c * 128 + kc * 32 + 2 * q;
        v0 = W2[(size_t)k0 * ZD + n];
        v1 = W2[(size_t)(k0 + 1) * ZD + n];
    }
    g_Wsl[idx] = packbf(v0, v1);
}
__global__ void write_out(float* __restrict__ out)
{
    out[0] = (float)(g_sum / (double)B_DIM);
}

// ---------------- host launcher ----------------
extern "C" void kernel_launch(void* const* d_in, const int* in_sizes, int n_in,
                              void* d_out, int out_size)
{
    (void)in_sizes; (void)n_in; (void)out_size;
    const float* ctx    = (const float*)d_in[0];
    const float* eps0   = (const float*)d_in[1];
    const float* eps    = (const float*)d_in[2];
    const float* beta   = (const float*)d_in[3];
    const float* sigma0 = (const float*)d_in[4];
    const float* W1     = (const float*)d_in[5];
    const float* b1     = (const float*)d_in[6];
    const float* W2     = (const float*)d_in[7];
    const float* b2     = (const float*)d_in[8];
    const float* temb   = (const float*)d_in[9];
    const float* tmu    = (const float*)d_in[10];
    float* out = (float*)d_out;

    cudaFuncSetAttribute(step_kernel, cudaFuncAttributeMaxDynamicSharedMemorySize, PS_SZ);

    prep_w1c<<<256, 256>>>(W1);
    prep_ctx<<<2048, 256>>>(ctx);
    prep_slices<<<256, 256>>>(W1, W2);
    ctxproj_kernel<<<dim3(4, 128), 256>>>(b1);
    step_kernel<<<128, 512, PS_SZ>>>(eps0, eps, beta, sigma0, b2, temb, tmu);
    write_out<<<1, 1>>>(out);
}

// round 9
// speedup vs baseline: 1.0244x; 1.0244x over previous
#include <cuda_runtime.h>
#include <cstdint>
#include <math.h>

#define B_DIM  16384
#define ZD     128
#define HD     512
#define TSTEPS 32

// ---------------- device global scratch ----------------
__device__ __align__(16) float    g_W1c[HD * HD];               // W1[128:640,:] tf32 (ctxproj)
__device__ __align__(16) float    g_ctxr[(size_t)B_DIM * HD];   // ctx tf32 (ctxproj)
__device__ __align__(16) uint32_t g_ctxpb[(size_t)B_DIM * 256]; // ctxproj, packed bf16x2 pairs
__device__ __align__(16) uint32_t g_Wsl[32 * 2048];             // 32 weight slices, bf16x2 [128n][16q]
__device__ double g_sum;

// ---------------- helpers ----------------
__device__ __forceinline__ float rna(float x) {
    float r; asm("cvt.rna.tf32.f32 %0, %1;" : "=f"(r) : "f"(x)); return r;
}
__device__ __forceinline__ uint32_t packbf(float lo, float hi) {
    uint32_t r; asm("cvt.rn.bf16x2.f32 %0, %1, %2;" : "=r"(r) : "f"(hi), "f"(lo)); return r;
}
__device__ __forceinline__ float bflo(uint32_t u) { return __uint_as_float(u << 16); }
__device__ __forceinline__ float bfhi(uint32_t u) { return __uint_as_float(u & 0xFFFF0000u); }
__device__ __forceinline__ uint32_t sptr(const void* p) {
    return (uint32_t)__cvta_generic_to_shared(p);
}
__device__ __forceinline__ void cp16(uint32_t d, const void* s) {
    asm volatile("cp.async.cg.shared.global [%0], [%1], 16;" :: "r"(d), "l"(s));
}
#define CP_COMMIT() asm volatile("cp.async.commit_group;" ::: "memory")

__device__ __forceinline__ void ldsm4(uint32_t r[4], uint32_t addr) {
    asm volatile("ldmatrix.sync.aligned.m8n8.x4.shared.b16 {%0,%1,%2,%3}, [%4];"
        : "=r"(r[0]), "=r"(r[1]), "=r"(r[2]), "=r"(r[3]) : "r"(addr));
}

#define MMA_TF32(acc, af, bf) \
    asm volatile("mma.sync.aligned.m16n8k8.row.col.f32.tf32.tf32.f32 " \
        "{%0,%1,%2,%3}, {%4,%5,%6,%7}, {%8,%9}, {%0,%1,%2,%3};" \
        : "+f"((acc)[0]), "+f"((acc)[1]), "+f"((acc)[2]), "+f"((acc)[3]) \
        : "r"((af)[0]), "r"((af)[1]), "r"((af)[2]), "r"((af)[3]), \
          "r"((bf)[0]), "r"((bf)[1]))

#define MMA_BF16(acc, af, b0, b1) \
    asm volatile("mma.sync.aligned.m16n8k16.row.col.f32.bf16.bf16.f32 " \
        "{%0,%1,%2,%3}, {%4,%5,%6,%7}, {%8,%9}, {%0,%1,%2,%3};" \
        : "+f"((acc)[0]), "+f"((acc)[1]), "+f"((acc)[2]), "+f"((acc)[3]) \
        : "r"((af)[0]), "r"((af)[1]), "r"((af)[2]), "r"((af)[3]), \
          "r"(b0), "r"(b1))

// ================= ctxproj tf32 GEMM (proven core, unchanged) =================
#define ASTR 20
#define BSTR 136

struct SmemT {
    float As[2][128][ASTR];
    float Bs[2][16][BSTR];
};

__device__ __forceinline__ void gemm_core(
    SmemT* s, const float* __restrict__ A, int lda,
    const float* __restrict__ Bm, int ldb, int K, float acc[2][8][4])
{
    const int tid = threadIdx.x;
    const int lane = tid & 31;
    const int w = tid >> 5, wm = w >> 1, wn = w & 1;
    const int nch = K / 16;

    #pragma unroll
    for (int i = 0; i < 2; i++) {
        int lin = tid + i * 256;
        int r = lin >> 2, kq = (lin & 3) * 4;
        cp16(sptr(&s->As[0][r][kq]), A + (size_t)r * lda + kq);
    }
    #pragma unroll
    for (int i = 0; i < 2; i++) {
        int lin = tid + i * 256;
        int kr = lin >> 5, nq = (lin & 31) * 4;
        cp16(sptr(&s->Bs[0][kr][nq]), Bm + (size_t)kr * ldb + nq);
    }
    CP_COMMIT();

    for (int c = 0; c < nch; c++) {
        const int buf = c & 1;
        if (c + 1 < nch) {
            const int k0 = (c + 1) * 16;
            #pragma unroll
            for (int i = 0; i < 2; i++) {
                int lin = tid + i * 256;
                int r = lin >> 2, kq = (lin & 3) * 4;
                cp16(sptr(&s->As[buf ^ 1][r][kq]), A + (size_t)r * lda + k0 + kq);
            }
            #pragma unroll
            for (int i = 0; i < 2; i++) {
                int lin = tid + i * 256;
                int kr = lin >> 5, nq = (lin & 31) * 4;
                cp16(sptr(&s->Bs[buf ^ 1][kr][nq]), Bm + (size_t)(k0 + kr) * ldb + nq);
            }
            CP_COMMIT();
            asm volatile("cp.async.wait_group 1;" ::: "memory");
        } else {
            asm volatile("cp.async.wait_group 0;" ::: "memory");
        }
        __syncthreads();

        #pragma unroll
        for (int kk = 0; kk < 16; kk += 8) {
            uint32_t af[2][4], bf[8][2];
            const int kb = kk + (lane & 3);
            #pragma unroll
            for (int mt = 0; mt < 2; mt++) {
                int r = wm * 32 + mt * 16 + (lane >> 2);
                af[mt][0] = __float_as_uint(s->As[buf][r][kb]);
                af[mt][1] = __float_as_uint(s->As[buf][r + 8][kb]);
                af[mt][2] = __float_as_uint(s->As[buf][r][kb + 4]);
                af[mt][3] = __float_as_uint(s->As[buf][r + 8][kb + 4]);
            }
            #pragma unroll
            for (int nt = 0; nt < 8; nt++) {
                int nn = wn * 64 + nt * 8 + (lane >> 2);
                bf[nt][0] = __float_as_uint(s->Bs[buf][kb][nn]);
                bf[nt][1] = __float_as_uint(s->Bs[buf][kb + 4][nn]);
            }
            #pragma unroll
            for (int mt = 0; mt < 2; mt++)
                #pragma unroll
                for (int nt = 0; nt < 8; nt++)
                    MMA_TF32(acc[mt][nt], af[mt], bf[nt]);
        }
        __syncthreads();
    }
}

__global__ void __launch_bounds__(256, 2) ctxproj_kernel(const float* __restrict__ b1)
{
    __shared__ SmemT s;
    float acc[2][8][4] = {};
    const int brow = blockIdx.y, bcol = blockIdx.x;
    gemm_core(&s, g_ctxr + (size_t)brow * 128 * HD, HD, g_W1c + bcol * 128, HD, HD, acc);

    const int lane = threadIdx.x & 31;
    const int w = threadIdx.x >> 5, wm = w >> 1, wn = w & 1;
    #pragma unroll
    for (int mt = 0; mt < 2; mt++) {
        #pragma unroll
        for (int nt = 0; nt < 8; nt++) {
            int r = brow * 128 + wm * 32 + mt * 16 + (lane >> 2);
            int c = bcol * 128 + wn * 64 + nt * 8 + 2 * (lane & 3);
            float2 bv = *reinterpret_cast<const float2*>(&b1[c]);
            g_ctxpb[(size_t)r * 256 + (c >> 1)] =
                packbf(acc[mt][nt][0] + bv.x, acc[mt][nt][1] + bv.y);
            g_ctxpb[(size_t)(r + 8) * 256 + (c >> 1)] =
                packbf(acc[mt][nt][2] + bv.x, acc[mt][nt][3] + bv.y);
        }
    }
}

// ================= persistent bf16 step kernel =================
// 8 warps (4m x 2n), warp tile 32x64, CTA tile 128 rows.
struct PS {
    float    zf[128][130];    // fp32 z state           66560 B
    uint32_t zb[128][68];     // bf16x2 z pairs         34816 B
    uint32_t hb[128][68];     // bf16x2 h chunk pairs   34816 B
    uint32_t wbT[5][128][20]; // weight ring, [n][kq]   51200 B
};
#define PS_SZ ((int)sizeof(PS))

extern __shared__ char dynsm[];

// A: base sptr of [128][68] u32 array; B: base sptr of one wbT slot [128][20].
__device__ __forceinline__ void mma_slice_ldsm(
    float acc[2][8][4], uint32_t a_base, int qb, uint32_t b_base,
    int lane, int wm, int wn)
{
    // per-lane invariants
    const int a_row = wm * 32 + (lane & 15);         // + mt*16
    const int a_col = (lane >> 4) * 4;               // + qb + kt*8
    const int b_row = wn * 64 + lane;                // + grp*32
    #pragma unroll
    for (int kt = 0; kt < 2; kt++) {
        uint32_t af[2][4];
        #pragma unroll
        for (int mt = 0; mt < 2; mt++)
            ldsm4(af[mt], a_base + (uint32_t)(((a_row + mt * 16) * 68 + qb + kt * 8 + a_col) * 4));
        uint32_t bg[2][2][4];  // [grp][khalf][tile]
        #pragma unroll
        for (int grp = 0; grp < 2; grp++)
            #pragma unroll
            for (int kh = 0; kh < 2; kh++)
                ldsm4(bg[grp][kh], b_base + (uint32_t)(((b_row + grp * 32) * 20 + kt * 8 + kh * 4) * 4));
        #pragma unroll
        for (int nt = 0; nt < 8; nt++) {
            uint32_t b0 = bg[nt >> 2][0][nt & 3];
            uint32_t b1 = bg[nt >> 2][1][nt & 3];
            #pragma unroll
            for (int mt = 0; mt < 2; mt++)
                MMA_BF16(acc[mt][nt], af[mt], b0, b1);
        }
    }
}

__global__ void __launch_bounds__(256, 1) step_kernel(
    const float* __restrict__ eps0, const float* __restrict__ eps,
    const float* __restrict__ beta, const float* __restrict__ sigma0,
    const float* __restrict__ b2,   const float* __restrict__ temb,
    const float* __restrict__ tmu)
{
    PS* s = (PS*)dynsm;
    const int tid = threadIdx.x, lane = tid & 31, w = tid >> 5;
    const int wm = w >> 1, wn = w & 1;
    const int grow0 = blockIdx.x * 128;
    const uint32_t zb_base = sptr(&s->zb[0][0]);
    const uint32_t hb_base = sptr(&s->hb[0][0]);

    const float s0 = sigma0[0];
    const float lg = logf(s0);
    const float dt = 1.0f / TSTEPS;
    double ssum = 0.0;

    // ---- init z (fp32 + bf16 copy) + prior-correction term ----
    {
        float local = 0.f;
        #pragma unroll
        for (int i = 0; i < 16; i++) {
            int lin = (tid + i * 256) * 4;
            int row = lin >> 7, col = lin & 127;
            float4 e = *reinterpret_cast<const float4*>(&eps0[(size_t)(grow0 + row) * ZD + col]);
            float z0 = s0 * e.x, z1 = s0 * e.y, z2 = s0 * e.z, z3 = s0 * e.w;
            s->zf[row][col + 0] = z0; s->zf[row][col + 1] = z1;
            s->zf[row][col + 2] = z2; s->zf[row][col + 3] = z3;
            s->zb[row][(col >> 1) + 0] = packbf(z0, z1);
            s->zb[row][(col >> 1) + 1] = packbf(z2, z3);
            local += 0.5f * (e.x * e.x + e.y * e.y + e.z * e.z + e.w * e.w) + 4.f * lg;
        }
        ssum += (double)local;
    }

    // ---- prologue: prefetch slices 0..3 into ring slots 0..3 ----
    #pragma unroll
    for (int g = 0; g < 4; g++) {
        const uint32_t* src = g_Wsl + (g & 31) * 2048;
        #pragma unroll
        for (int i = 0; i < 2; i++) {
            int lin = tid + i * 256;              // 0..511
            int n = lin >> 2, kq4 = (lin & 3) * 4;
            cp16(sptr(&s->wbT[g % 5][n][kq4]), src + n * 16 + kq4);
        }
        CP_COMMIT();
    }

#define SLICE_PRE(gv) do { \
    asm volatile("cp.async.wait_group 3;" ::: "memory"); \
    __syncthreads(); \
    const uint32_t* _src = g_Wsl + (((gv) + 4) & 31) * 2048; \
    uint32_t* _dstrow = &s->wbT[((gv) + 4) % 5][0][0]; \
    _Pragma("unroll") \
    for (int _i = 0; _i < 2; _i++) { \
        int _lin = tid + _i * 256; \
        int _n = _lin >> 2, _k = (_lin & 3) * 4; \
        cp16(sptr(_dstrow + _n * 20 + _k), _src + _n * 16 + _k); \
    } \
    CP_COMMIT(); \
} while (0)

    int g = 0;
    for (int t = 0; t < TSTEPS; t++) {
        const float beta_f = __ldg(&beta[t]);
        const float beta_b = __ldg(&beta[(t + TSTEPS - 1) % TSTEPS]);
        const float sig_f = sqrtf(2.0f * beta_f * dt) * s0;
        const float sig_b = sqrtf(2.0f * beta_b * dt) * s0;
        const float inv_sb = 1.0f / sig_b;
        const float logdiff = logf(sig_f) - logf(sig_b);

        float accu[2][8][4] = {};

        for (int c = 0; c < 4; c++) {
            float acch[2][8][4] = {};
            #pragma unroll
            for (int kc = 0; kc < 4; kc++) {
                SLICE_PRE(g);
                mma_slice_ldsm(acch, zb_base, kc * 16,
                               sptr(&s->wbT[g % 5][0][0]), lane, wm, wn);
                g++;
            }
            // ---- epilogue1: h = bf16(relu(acch + ctxp + te)) -> hb ----
            // batch ctxpb loads first (MLP)
            uint32_t cpr[8][2][2];
            #pragma unroll
            for (int nt = 0; nt < 8; nt++) {
                int lq = wn * 32 + nt * 4 + (lane & 3);
                #pragma unroll
                for (int mt = 0; mt < 2; mt++) {
                    int r = wm * 32 + mt * 16 + (lane >> 2);
                    cpr[nt][mt][0] = __ldg(&g_ctxpb[(size_t)(grow0 + r) * 256 + c * 64 + lq]);
                    cpr[nt][mt][1] = __ldg(&g_ctxpb[(size_t)(grow0 + r + 8) * 256 + c * 64 + lq]);
                }
            }
            #pragma unroll
            for (int nt = 0; nt < 8; nt++) {
                int gc = c * 128 + wn * 64 + nt * 8 + 2 * (lane & 3);
                float2 te = *reinterpret_cast<const float2*>(&temb[(size_t)t * HD + gc]);
                int lq = wn * 32 + nt * 4 + (lane & 3);
                #pragma unroll
                for (int mt = 0; mt < 2; mt++) {
                    int r = wm * 32 + mt * 16 + (lane >> 2);
                    #pragma unroll
                    for (int hf = 0; hf < 2; hf++) {
                        int rr = r + 8 * hf;
                        uint32_t cpv = cpr[nt][mt][hf];
                        float v0 = acch[mt][nt][hf * 2 + 0] + bflo(cpv) + te.x;
                        float v1 = acch[mt][nt][hf * 2 + 1] + bfhi(cpv) + te.y;
                        s->hb[rr][lq] = packbf(fmaxf(v0, 0.f), fmaxf(v1, 0.f));
                    }
                }
            }
            #pragma unroll
            for (int kc = 0; kc < 4; kc++) {
                SLICE_PRE(g);
                mma_slice_ldsm(accu, hb_base, kc * 16,
                               sptr(&s->wbT[g % 5][0][0]), lane, wm, wn);
                g++;
            }
        }

        // ---- update epilogue ----
        const float* eps_t = eps + ((size_t)t * B_DIM + grow0) * ZD;
        float local = 0.f;
        #pragma unroll
        for (int nt = 0; nt < 8; nt++) {
            int cc = wn * 64 + nt * 8 + 2 * (lane & 3);
            float2 bv = *reinterpret_cast<const float2*>(&b2[cc]);
            #pragma unroll
            for (int mt = 0; mt < 2; mt++) {
                int r = wm * 32 + mt * 16 + (lane >> 2);
                #pragma unroll
                for (int hf = 0; hf < 2; hf++) {
                    int rr = r + 8 * hf;
                    float2 zp = *reinterpret_cast<const float2*>(&s->zf[rr][cc]);
                    float2 ev = *reinterpret_cast<const float2*>(&eps_t[(size_t)rr * ZD + cc]);
                    float u0 = accu[mt][nt][hf * 2 + 0] + bv.x;
                    float u1 = accu[mt][nt][hf * 2 + 1] + bv.y;
                    float mu0 = zp.x + (beta_f * zp.x + u0) * dt;
                    float mu1 = zp.y + (beta_f * zp.y + u1) * dt;
                    float zn0 = fmaf(sig_f, ev.x, mu0);
                    float zn1 = fmaf(sig_f, ev.y, mu1);
                    float mb0 = zn0 - beta_b * zn0 * dt;
                    float mb1 = zn1 - beta_b * zn1 * dt;
                    float a10 = (zp.x - mb0) * inv_sb;
                    float a11 = (zp.y - mb1) * inv_sb;
                    local += 0.5f * (ev.x * ev.x - a10 * a10) + logdiff;
                    local += 0.5f * (ev.y * ev.y - a11 * a11) + logdiff;
                    if (t == TSTEPS - 1) {
                        float2 tm = *reinterpret_cast<const float2*>(
                            &tmu[(size_t)(grow0 + rr) * ZD + cc]);
                        float d0 = zn0 - tm.x, d1 = zn1 - tm.y;
                        local -= 0.5f * (d0 * d0 + d1 * d1);
                    }
                    float2 zo = { zn0, zn1 };
                    *reinterpret_cast<float2*>(&s->zf[rr][cc]) = zo;
                    s->zb[rr][cc >> 1] = packbf(zn0, zn1);
                }
            }
        }
        ssum += (double)local;
    }

    // ---- reduce ----
    asm volatile("cp.async.wait_group 0;" ::: "memory");
    __syncthreads();
    double* red = reinterpret_cast<double*>(&s->wbT[0][0][0]);
    red[tid] = ssum;
    __syncthreads();
    for (int st = 128; st > 0; st >>= 1) {
        if (tid < st) red[tid] += red[tid + st];
        __syncthreads();
    }
    if (tid == 0) atomicAdd(&g_sum, red[0]);
}

// ---------------- prep / finalize ----------------
__global__ void prep_w1c(const float* __restrict__ W1)
{
    const int N = HD * HD;
    for (int i = blockIdx.x * blockDim.x + threadIdx.x; i < N; i += gridDim.x * blockDim.x)
        g_W1c[i] = rna(W1[ZD * HD + i]);
}
__global__ void prep_ctx(const float* __restrict__ ctx)
{
    const size_t N = (size_t)B_DIM * HD;
    size_t i0 = (size_t)blockIdx.x * blockDim.x + threadIdx.x;
    if (i0 == 0) g_sum = 0.0;
    for (size_t i = i0; i < N; i += (size_t)gridDim.x * blockDim.x)
        g_ctxr[i] = rna(ctx[i]);
}
// build packed bf16 weight slices (layout [128n][16q]):
// slice si: c=si>>3, ph=(si>>2)&1, kc=si&3; word idx = n*16 + q
__global__ void prep_slices(const float* __restrict__ W1, const float* __restrict__ W2)
{
    int idx = blockIdx.x * blockDim.x + threadIdx.x;
    if (idx >= 32 * 2048) return;
    int si = idx >> 11, rem = idx & 2047;
    int n = rem >> 4, q = rem & 15;
    int c = si >> 3, ph = (si >> 2) & 1, kc = si & 3;
    float v0, v1;
    if (!ph) {
        int k0 = kc * 32 + 2 * q;
        v0 = W1[(size_t)k0 * HD + c * 128 + n];
        v1 = W1[(size_t)(k0 + 1) * HD + c * 128 + n];
    } else {
        int k0 = c * 128 + kc * 32 + 2 * q;
        v0 = W2[(size_t)k0 * ZD + n];
        v1 = W2[(size_t)(k0 + 1) * ZD + n];
    }
    g_Wsl[idx] = packbf(v0, v1);
}
__global__ void write_out(float* __restrict__ out)
{
    out[0] = (float)(g_sum / (double)B_DIM);
}

// ---------------- host launcher ----------------
extern "C" void kernel_launch(void* const* d_in, const int* in_sizes, int n_in,
                              void* d_out, int out_size)
{
    (void)in_sizes; (void)n_in; (void)out_size;
    const float* ctx    = (const float*)d_in[0];
    const float* eps0   = (const float*)d_in[1];
    const float* eps    = (const float*)d_in[2];
    const float* beta   = (const float*)d_in[3];
    const float* sigma0 = (const float*)d_in[4];
    const float* W1     = (const float*)d_in[5];
    const float* b1     = (const float*)d_in[6];
    const float* W2     = (const float*)d_in[7];
    const float* b2     = (const float*)d_in[8];
    const float* temb   = (const float*)d_in[9];
    const float* tmu    = (const float*)d_in[10];
    float* out = (float*)d_out;

    cudaFuncSetAttribute(step_kernel, cudaFuncAttributeMaxDynamicSharedMemorySize, PS_SZ);

    prep_w1c<<<256, 256>>>(W1);
    prep_ctx<<<2048, 256>>>(ctx);
    prep_slices<<<256, 256>>>(W1, W2);
    ctxproj_kernel<<<dim3(4, 128), 256>>>(b1);
    step_kernel<<<128, 256, PS_SZ>>>(eps0, eps, beta, sigma0, b2, temb, tmu);
    write_out<<<1, 1>>>(out);
}

// round 10
// speedup vs baseline: 1.1178x; 1.0912x over previous
#include <cuda_runtime.h>
#include <cstdint>
#include <math.h>

#define B_DIM  16384
#define ZD     128
#define HD     512
#define TSTEPS 32

// ---------------- device global scratch ----------------
__device__ __align__(16) float    g_W1c[HD * HD];               // W1[128:640,:] tf32 (ctxproj)
__device__ __align__(16) float    g_ctxr[(size_t)B_DIM * HD];   // ctx tf32 (ctxproj)
__device__ __align__(16) uint32_t g_ctxpb[(size_t)B_DIM * 256]; // ctxproj, packed bf16x2 pairs
__device__ __align__(16) uint32_t g_Wsl[32 * 2048];             // 32 weight slices, bf16x2 [16q][128n]
__device__ double g_sum;

// ---------------- helpers ----------------
__device__ __forceinline__ float rna(float x) {
    float r; asm("cvt.rna.tf32.f32 %0, %1;" : "=f"(r) : "f"(x)); return r;
}
__device__ __forceinline__ uint32_t packbf(float lo, float hi) {
    uint32_t r; asm("cvt.rn.bf16x2.f32 %0, %1, %2;" : "=r"(r) : "f"(hi), "f"(lo)); return r;
}
__device__ __forceinline__ float bflo(uint32_t u) { return __uint_as_float(u << 16); }
__device__ __forceinline__ float bfhi(uint32_t u) { return __uint_as_float(u & 0xFFFF0000u); }
__device__ __forceinline__ uint32_t sptr(const void* p) {
    return (uint32_t)__cvta_generic_to_shared(p);
}
__device__ __forceinline__ void cp16(uint32_t d, const void* s) {
    asm volatile("cp.async.cg.shared.global [%0], [%1], 16;" :: "r"(d), "l"(s));
}
#define CP_COMMIT() asm volatile("cp.async.commit_group;" ::: "memory")

#define MMA_TF32(acc, af, bf) \
    asm volatile("mma.sync.aligned.m16n8k8.row.col.f32.tf32.tf32.f32 " \
        "{%0,%1,%2,%3}, {%4,%5,%6,%7}, {%8,%9}, {%0,%1,%2,%3};" \
        : "+f"((acc)[0]), "+f"((acc)[1]), "+f"((acc)[2]), "+f"((acc)[3]) \
        : "r"((af)[0]), "r"((af)[1]), "r"((af)[2]), "r"((af)[3]), \
          "r"((bf)[0]), "r"((bf)[1]))

#define MMA_BF16(acc, af, b0, b1) \
    asm volatile("mma.sync.aligned.m16n8k16.row.col.f32.bf16.bf16.f32 " \
        "{%0,%1,%2,%3}, {%4,%5,%6,%7}, {%8,%9}, {%0,%1,%2,%3};" \
        : "+f"((acc)[0]), "+f"((acc)[1]), "+f"((acc)[2]), "+f"((acc)[3]) \
        : "r"((af)[0]), "r"((af)[1]), "r"((af)[2]), "r"((af)[3]), \
          "r"(b0), "r"(b1))

// ================= ctxproj tf32 GEMM (proven core, unchanged) =================
#define ASTR 20
#define BSTR 136

struct SmemT {
    float As[2][128][ASTR];
    float Bs[2][16][BSTR];
};

__device__ __forceinline__ void gemm_core(
    SmemT* s, const float* __restrict__ A, int lda,
    const float* __restrict__ Bm, int ldb, int K, float acc[2][8][4])
{
    const int tid = threadIdx.x;
    const int lane = tid & 31;
    const int w = tid >> 5, wm = w >> 1, wn = w & 1;
    const int nch = K / 16;

    #pragma unroll
    for (int i = 0; i < 2; i++) {
        int lin = tid + i * 256;
        int r = lin >> 2, kq = (lin & 3) * 4;
        cp16(sptr(&s->As[0][r][kq]), A + (size_t)r * lda + kq);
    }
    #pragma unroll
    for (int i = 0; i < 2; i++) {
        int lin = tid + i * 256;
        int kr = lin >> 5, nq = (lin & 31) * 4;
        cp16(sptr(&s->Bs[0][kr][nq]), Bm + (size_t)kr * ldb + nq);
    }
    CP_COMMIT();

    for (int c = 0; c < nch; c++) {
        const int buf = c & 1;
        if (c + 1 < nch) {
            const int k0 = (c + 1) * 16;
            #pragma unroll
            for (int i = 0; i < 2; i++) {
                int lin = tid + i * 256;
                int r = lin >> 2, kq = (lin & 3) * 4;
                cp16(sptr(&s->As[buf ^ 1][r][kq]), A + (size_t)r * lda + k0 + kq);
            }
            #pragma unroll
            for (int i = 0; i < 2; i++) {
                int lin = tid + i * 256;
                int kr = lin >> 5, nq = (lin & 31) * 4;
                cp16(sptr(&s->Bs[buf ^ 1][kr][nq]), Bm + (size_t)(k0 + kr) * ldb + nq);
            }
            CP_COMMIT();
            asm volatile("cp.async.wait_group 1;" ::: "memory");
        } else {
            asm volatile("cp.async.wait_group 0;" ::: "memory");
        }
        __syncthreads();

        #pragma unroll
        for (int kk = 0; kk < 16; kk += 8) {
            uint32_t af[2][4], bf[8][2];
            const int kb = kk + (lane & 3);
            #pragma unroll
            for (int mt = 0; mt < 2; mt++) {
                int r = wm * 32 + mt * 16 + (lane >> 2);
                af[mt][0] = __float_as_uint(s->As[buf][r][kb]);
                af[mt][1] = __float_as_uint(s->As[buf][r + 8][kb]);
                af[mt][2] = __float_as_uint(s->As[buf][r][kb + 4]);
                af[mt][3] = __float_as_uint(s->As[buf][r + 8][kb + 4]);
            }
            #pragma unroll
            for (int nt = 0; nt < 8; nt++) {
                int nn = wn * 64 + nt * 8 + (lane >> 2);
                bf[nt][0] = __float_as_uint(s->Bs[buf][kb][nn]);
                bf[nt][1] = __float_as_uint(s->Bs[buf][kb + 4][nn]);
            }
            #pragma unroll
            for (int mt = 0; mt < 2; mt++)
                #pragma unroll
                for (int nt = 0; nt < 8; nt++)
                    MMA_TF32(acc[mt][nt], af[mt], bf[nt]);
        }
        __syncthreads();
    }
}

__global__ void __launch_bounds__(256, 2) ctxproj_kernel(const float* __restrict__ b1)
{
    __shared__ SmemT s;
    float acc[2][8][4] = {};
    const int brow = blockIdx.y, bcol = blockIdx.x;
    gemm_core(&s, g_ctxr + (size_t)brow * 128 * HD, HD, g_W1c + bcol * 128, HD, HD, acc);

    const int lane = threadIdx.x & 31;
    const int w = threadIdx.x >> 5, wm = w >> 1, wn = w & 1;
    #pragma unroll
    for (int mt = 0; mt < 2; mt++) {
        #pragma unroll
        for (int nt = 0; nt < 8; nt++) {
            int r = brow * 128 + wm * 32 + mt * 16 + (lane >> 2);
            int c = bcol * 128 + wn * 64 + nt * 8 + 2 * (lane & 3);
            float2 bv = *reinterpret_cast<const float2*>(&b1[c]);
            g_ctxpb[(size_t)r * 256 + (c >> 1)] =
                packbf(acc[mt][nt][0] + bv.x, acc[mt][nt][1] + bv.y);
            g_ctxpb[(size_t)(r + 8) * 256 + (c >> 1)] =
                packbf(acc[mt][nt][2] + bv.x, acc[mt][nt][3] + bv.y);
        }
    }
}

// ================= persistent bf16 step kernel =================
// 8 warps (4m x 2n), warp tile 32x64, CTA tile 128 rows.
// Weight ring: 8 slots = 2 groups of 4 slices; 1 barrier + 1 wait per group.
struct PS {
    float    zf[128][130];    // fp32 z state           66560 B
    uint32_t zb[128][68];     // bf16x2 z pairs         34816 B
    uint32_t hb[128][68];     // bf16x2 h chunk pairs   34816 B
    uint32_t wb[8][16][136];  // weight slice ring      69632 B
};
#define PS_SZ ((int)sizeof(PS))

extern __shared__ char dynsm[];

__device__ __forceinline__ void mma_slice(
    float acc[2][8][4], const uint32_t (&A)[128][68], int qb,
    const uint32_t (&Bm)[16][136], int lane, int wm, int wn)
{
    #pragma unroll
    for (int kt = 0; kt < 2; kt++) {
        const int qa = qb + kt * 8 + (lane & 3);
        uint32_t af[2][4];
        #pragma unroll
        for (int mt = 0; mt < 2; mt++) {
            int r = wm * 32 + mt * 16 + (lane >> 2);
            af[mt][0] = A[r][qa];
            af[mt][1] = A[r + 8][qa];
            af[mt][2] = A[r][qa + 4];
            af[mt][3] = A[r + 8][qa + 4];
        }
        const int kq = kt * 8 + (lane & 3);
        #pragma unroll
        for (int nt = 0; nt < 8; nt++) {
            int nn = wn * 64 + nt * 8 + (lane >> 2);
            uint32_t b0 = Bm[kq][nn];
            uint32_t b1 = Bm[kq + 4][nn];
            #pragma unroll
            for (int mt = 0; mt < 2; mt++)
                MMA_BF16(acc[mt][nt], af[mt], b0, b1);
        }
    }
}

__global__ void __launch_bounds__(256, 1) step_kernel(
    const float* __restrict__ eps0, const float* __restrict__ eps,
    const float* __restrict__ beta, const float* __restrict__ sigma0,
    const float* __restrict__ b2,   const float* __restrict__ temb,
    const float* __restrict__ tmu)
{
    PS* s = (PS*)dynsm;
    const int tid = threadIdx.x, lane = tid & 31, w = tid >> 5;
    const int wm = w >> 1, wn = w & 1;
    const int grow0 = blockIdx.x * 128;

    const float s0 = sigma0[0];
    const float lg = logf(s0);
    const float dt = 1.0f / TSTEPS;
    double ssum = 0.0;

    // ---- init z (fp32 + bf16 copy) + prior-correction term ----
    {
        float local = 0.f;
        #pragma unroll
        for (int i = 0; i < 16; i++) {
            int lin = (tid + i * 256) * 4;
            int row = lin >> 7, col = lin & 127;
            float4 e = *reinterpret_cast<const float4*>(&eps0[(size_t)(grow0 + row) * ZD + col]);
            float z0 = s0 * e.x, z1 = s0 * e.y, z2 = s0 * e.z, z3 = s0 * e.w;
            s->zf[row][col + 0] = z0; s->zf[row][col + 1] = z1;
            s->zf[row][col + 2] = z2; s->zf[row][col + 3] = z3;
            s->zb[row][(col >> 1) + 0] = packbf(z0, z1);
            s->zb[row][(col >> 1) + 1] = packbf(z2, z3);
            local += 0.5f * (e.x * e.x + e.y * e.y + e.z * e.z + e.w * e.w) + 4.f * lg;
        }
        ssum += (double)local;
    }

// issue one group (4 slices = 32KB) into ring half (gv&1)
#define ISSUE_GROUP(gv) do { \
    const uint32_t* _src = g_Wsl + ((gv) & 7) * 8192; \
    const int _slot0 = ((gv) & 1) * 4; \
    _Pragma("unroll") \
    for (int _i = 0; _i < 8; _i++) { \
        int _j = tid + _i * 256; \
        int _sl = _j >> 9, _rem = _j & 511; \
        cp16(sptr(&s->wb[_slot0 + _sl][_rem >> 5][(_rem & 31) * 4]), \
             _src + _sl * 2048 + _rem * 4); \
    } \
    CP_COMMIT(); \
} while (0)

// wait for the group we're about to consume (issued one group ago), barrier
#define GROUP_SYNC() do { \
    asm volatile("cp.async.wait_group 0;" ::: "memory"); \
    __syncthreads(); \
} while (0)

    // prologue: issue group 0
    ISSUE_GROUP(0);

    int g = 0;
    for (int t = 0; t < TSTEPS; t++) {
        const float beta_f = __ldg(&beta[t]);
        const float beta_b = __ldg(&beta[(t + TSTEPS - 1) % TSTEPS]);
        const float sig_f = sqrtf(2.0f * beta_f * dt) * s0;
        const float sig_b = sqrtf(2.0f * beta_b * dt) * s0;
        const float inv_sb = 1.0f / sig_b;
        const float logdiff = logf(sig_f) - logf(sig_b);

        float accu[2][8][4] = {};

        for (int c = 0; c < 4; c++) {
            // ---- MMA1 group: acch = z @ W1a[:, c] ----
            float acch[2][8][4] = {};
            GROUP_SYNC();
            ISSUE_GROUP(g + 1);
            {
                const int slot0 = (g & 1) * 4;
                #pragma unroll
                for (int kc = 0; kc < 4; kc++)
                    mma_slice(acch, s->zb, kc * 16, s->wb[slot0 + kc], lane, wm, wn);
            }
            g++;
            // ---- epilogue1: h = bf16(relu(acch + ctxp + te)) -> hb ----
            #pragma unroll
            for (int nt = 0; nt < 8; nt++) {
                int gc = c * 128 + wn * 64 + nt * 8 + 2 * (lane & 3);
                float2 te = *reinterpret_cast<const float2*>(&temb[(size_t)t * HD + gc]);
                int lq = wn * 32 + nt * 4 + (lane & 3);
                #pragma unroll
                for (int mt = 0; mt < 2; mt++) {
                    int r = wm * 32 + mt * 16 + (lane >> 2);
                    #pragma unroll
                    for (int hf = 0; hf < 2; hf++) {
                        int rr = r + 8 * hf;
                        uint32_t cpv = __ldg(&g_ctxpb[(size_t)(grow0 + rr) * 256 + c * 64 + lq]);
                        float v0 = acch[mt][nt][hf * 2 + 0] + bflo(cpv) + te.x;
                        float v1 = acch[mt][nt][hf * 2 + 1] + bfhi(cpv) + te.y;
                        s->hb[rr][lq] = packbf(fmaxf(v0, 0.f), fmaxf(v1, 0.f));
                    }
                }
            }
            // ---- MMA2 group: accu += h @ W2[c, :] ----
            GROUP_SYNC();
            ISSUE_GROUP(g + 1);
            {
                const int slot0 = (g & 1) * 4;
                #pragma unroll
                for (int kc = 0; kc < 4; kc++)
                    mma_slice(accu, s->hb, kc * 16, s->wb[slot0 + kc], lane, wm, wn);
            }
            g++;
        }

        // ---- update epilogue ----
        const float* eps_t = eps + ((size_t)t * B_DIM + grow0) * ZD;
        float local = 0.f;
        #pragma unroll
        for (int nt = 0; nt < 8; nt++) {
            int cc = wn * 64 + nt * 8 + 2 * (lane & 3);
            float2 bv = *reinterpret_cast<const float2*>(&b2[cc]);
            #pragma unroll
            for (int mt = 0; mt < 2; mt++) {
                int r = wm * 32 + mt * 16 + (lane >> 2);
                #pragma unroll
                for (int hf = 0; hf < 2; hf++) {
                    int rr = r + 8 * hf;
                    float2 zp = *reinterpret_cast<const float2*>(&s->zf[rr][cc]);
                    float2 ev = *reinterpret_cast<const float2*>(&eps_t[(size_t)rr * ZD + cc]);
                    float u0 = accu[mt][nt][hf * 2 + 0] + bv.x;
                    float u1 = accu[mt][nt][hf * 2 + 1] + bv.y;
                    float mu0 = zp.x + (beta_f * zp.x + u0) * dt;
                    float mu1 = zp.y + (beta_f * zp.y + u1) * dt;
                    float zn0 = fmaf(sig_f, ev.x, mu0);
                    float zn1 = fmaf(sig_f, ev.y, mu1);
                    float mb0 = zn0 - beta_b * zn0 * dt;
                    float mb1 = zn1 - beta_b * zn1 * dt;
                    float a10 = (zp.x - mb0) * inv_sb;
                    float a11 = (zp.y - mb1) * inv_sb;
                    local += 0.5f * (ev.x * ev.x - a10 * a10) + logdiff;
                    local += 0.5f * (ev.y * ev.y - a11 * a11) + logdiff;
                    if (t == TSTEPS - 1) {
                        float2 tm = *reinterpret_cast<const float2*>(
                            &tmu[(size_t)(grow0 + rr) * ZD + cc]);
                        float d0 = zn0 - tm.x, d1 = zn1 - tm.y;
                        local -= 0.5f * (d0 * d0 + d1 * d1);
                    }
                    float2 zo = { zn0, zn1 };
                    *reinterpret_cast<float2*>(&s->zf[rr][cc]) = zo;
                    s->zb[rr][cc >> 1] = packbf(zn0, zn1);
                }
            }
        }
        ssum += (double)local;
    }

    // ---- reduce ----
    asm volatile("cp.async.wait_group 0;" ::: "memory");
    __syncthreads();
    double* red = reinterpret_cast<double*>(&s->wb[0][0][0]);
    red[tid] = ssum;
    __syncthreads();
    for (int st = 128; st > 0; st >>= 1) {
        if (tid < st) red[tid] += red[tid + st];
        __syncthreads();
    }
    if (tid == 0) atomicAdd(&g_sum, red[0]);
}

// ---------------- prep / finalize ----------------
__global__ void prep_w1c(const float* __restrict__ W1)
{
    const int N = HD * HD;
    for (int i = blockIdx.x * blockDim.x + threadIdx.x; i < N; i += gridDim.x * blockDim.x)
        g_W1c[i] = rna(W1[ZD * HD + i]);
}
__global__ void prep_ctx(const float* __restrict__ ctx)
{
    const size_t N = (size_t)B_DIM * HD;
    size_t i0 = (size_t)blockIdx.x * blockDim.x + threadIdx.x;
    if (i0 == 0) g_sum = 0.0;
    for (size_t i = i0; i < N; i += (size_t)gridDim.x * blockDim.x)
        g_ctxr[i] = rna(ctx[i]);
}
// build packed bf16 weight slices: slice si: c=si>>3, ph=(si>>2)&1, kc=si&3
// slice layout [16q][128n]; word idx = q*128 + n
__global__ void prep_slices(const float* __restrict__ W1, const float* __restrict__ W2)
{
    int idx = blockIdx.x * blockDim.x + threadIdx.x;
    if (idx >= 32 * 2048) return;
    int si = idx >> 11, rem = idx & 2047;
    int q = rem >> 7, n = rem & 127;
    int c = si >> 3, ph = (si >> 2) & 1, kc = si & 3;
    float v0, v1;
    if (!ph) {
        int k0 = kc * 32 + 2 * q;
        v0 = W1[(size_t)k0 * HD + c * 128 + n];
        v1 = W1[(size_t)(k0 + 1) * HD + c * 128 + n];
    } else {
        int k0 = c * 128 + kc * 32 + 2 * q;
        v0 = W2[(size_t)k0 * ZD + n];
        v1 = W2[(size_t)(k0 + 1) * ZD + n];
    }
    g_Wsl[idx] = packbf(v0, v1);
}
__global__ void write_out(float* __restrict__ out)
{
    out[0] = (float)(g_sum / (double)B_DIM);
}

// ---------------- host launcher ----------------
extern "C" void kernel_launch(void* const* d_in, const int* in_sizes, int n_in,
                              void* d_out, int out_size)
{
    (void)in_sizes; (void)n_in; (void)out_size;
    const float* ctx    = (const float*)d_in[0];
    const float* eps0   = (const float*)d_in[1];
    const float* eps    = (const float*)d_in[2];
    const float* beta   = (const float*)d_in[3];
    const float* sigma0 = (const float*)d_in[4];
    const float* W1     = (const float*)d_in[5];
    const float* b1     = (const float*)d_in[6];
    const float* W2     = (const float*)d_in[7];
    const float* b2     = (const float*)d_in[8];
    const float* temb   = (const float*)d_in[9];
    const float* tmu    = (const float*)d_in[10];
    float* out = (float*)d_out;

    cudaFuncSetAttribute(step_kernel, cudaFuncAttributeMaxDynamicSharedMemorySize, PS_SZ);

    prep_w1c<<<256, 256>>>(W1);
    prep_ctx<<<2048, 256>>>(ctx);
    prep_slices<<<256, 256>>>(W1, W2);
    ctxproj_kernel<<<dim3(4, 128), 256>>>(b1);
    step_kernel<<<128, 256, PS_SZ>>>(eps0, eps, beta, sigma0, b2, temb, tmu);
    write_out<<<1, 1>>>(out);
}